// round 7
// baseline (speedup 1.0000x reference)
#include <cuda_runtime.h>

#define NB 8
#define NS 2048
#define NE 8
#define NH 2
#define ND 4
#define NT (NB*NS)        // 16384 tokens
#define NBH (NB*NH)       // 16 (batch, head) pairs
#define SPLITS 8
#define KPS (NS/SPLITS)   // 256 keys per split
#define NPAIR (KPS/2)     // 128 key pairs
#define QB 512            // queries per CTA (4 per thread)

// log2(e) / sqrt(D) folded into q so scores feed ex2 directly
#define QSCALE 0.72134752044448169f

// Accumulators (zero at module load; each launch leaves them zero again)
__device__ float4 g_accN[NT*NH];   // softmax numerators, index = token*2 + head
__device__ float  g_accD[NT*NH];   // softmax denominators

typedef unsigned long long ull;

// ---- packed f32x2 helpers ----
static __device__ __forceinline__ ull pack2(float a, float b) {
    ull r; asm("mov.b64 %0, {%1,%2};" : "=l"(r) : "f"(a), "f"(b)); return r;
}
static __device__ __forceinline__ void unpack2(ull v, float& a, float& b) {
    asm("mov.b64 {%0,%1}, %2;" : "=f"(a), "=f"(b) : "l"(v));
}
static __device__ __forceinline__ ull fma2p(ull a, ull b, ull c) {
    ull d; asm("fma.rn.f32x2 %0, %1, %2, %3;" : "=l"(d) : "l"(a), "l"(b), "l"(c)); return d;
}
static __device__ __forceinline__ ull mul2p(ull a, ull b) {
    ull d; asm("mul.rn.f32x2 %0, %1, %2;" : "=l"(d) : "l"(a), "l"(b)); return d;
}
static __device__ __forceinline__ float ex2f(float x) {
    float r; asm("ex2.approx.f32 %0, %1;" : "=f"(r) : "f"(x)); return r;
}
static __device__ __forceinline__ float rcpf(float x) {
    float r; asm("rcp.approx.f32 %0, %1;" : "=f"(r) : "f"(x)); return r;
}

// ============================================================
// Fused QKV + split-K softmax attention.
// grid = (NS/QB, SPLITS, NBH), 128 threads, 4 queries/thread.
// K/V staged key-pair-packed (SoA, conflict-free LDS.128).
// Inner iter: 4 LDS covering 8 scores (LDS/score = 0.5),
// 36 fma2 + 8 MUFU per 8 scores. Results reduced into global
// accumulators via REDG atomicAdd (no partial buffers).
// ============================================================
__global__ void __launch_bounds__(128) attn_kernel(const float* __restrict__ x,
                                                   const float* __restrict__ Wq,
                                                   const float* __restrict__ Wk,
                                                   const float* __restrict__ Wv) {
    __shared__ float sWq[32], sWk[32], sWv[32];   // this head's 4 rows (4x8)
    __shared__ ulonglong2 sK01[NPAIR];
    __shared__ ulonglong2 sK23[NPAIR];
    __shared__ ulonglong2 sV01[NPAIR];
    __shared__ ulonglong2 sV23[NPAIR];

    const int bh    = blockIdx.z;
    const int split = blockIdx.y;
    const int tid   = threadIdx.x;
    const int b     = bh >> 1;
    const int h     = bh & 1;

    if (tid < 32) {
        sWq[tid] = Wq[h*32 + tid];
        sWk[tid] = Wk[h*32 + tid];
        sWv[tid] = Wv[h*32 + tid];
    }
    __syncthreads();

    const float4* x4 = (const float4*)x;

    // ---- stage one key pair per thread (keys 2*tid, 2*tid+1) ----
    {
        int tokA = b*NS + split*KPS + 2*tid;
        float4 a0 = x4[tokA*2], a1 = x4[tokA*2+1];
        float4 b0 = x4[tokA*2+2], b1 = x4[tokA*2+3];
        float xra[8] = {a0.x,a0.y,a0.z,a0.w,a1.x,a1.y,a1.z,a1.w};
        float xrb[8] = {b0.x,b0.y,b0.z,b0.w,b1.x,b1.y,b1.z,b1.w};
        float kA[4], vA[4], kB[4], vB[4];
#pragma unroll
        for (int d = 0; d < 4; d++) {
            float ka = 0.f, va = 0.f, kb = 0.f, vb = 0.f;
#pragma unroll
            for (int e = 0; e < 8; e++) {
                float wk = sWk[d*8 + e], wv = sWv[d*8 + e];
                ka += xra[e] * wk;  va += xra[e] * wv;
                kb += xrb[e] * wk;  vb += xrb[e] * wv;
            }
            kA[d] = ka; vA[d] = va; kB[d] = kb; vB[d] = vb;
        }
        ulonglong2 t;
        t.x = pack2(kA[0], kB[0]); t.y = pack2(kA[1], kB[1]); sK01[tid] = t;
        t.x = pack2(kA[2], kB[2]); t.y = pack2(kA[3], kB[3]); sK23[tid] = t;
        t.x = pack2(vA[0], vB[0]); t.y = pack2(vA[1], vB[1]); sV01[tid] = t;
        t.x = pack2(vA[2], vB[2]); t.y = pack2(vA[3], vB[3]); sV23[tid] = t;
    }

    // ---- this thread's 4 queries (qi + 128*qq), {q,q}-dup packed ----
    const int qi = blockIdx.x * QB + tid;
    ull q[4][4];
#pragma unroll
    for (int qq = 0; qq < 4; qq++) {
        int ta = b*NS + qi + qq*128;
        float4 a0 = x4[ta*2], a1 = x4[ta*2+1];
        float xr[8] = {a0.x,a0.y,a0.z,a0.w,a1.x,a1.y,a1.z,a1.w};
#pragma unroll
        for (int d = 0; d < 4; d++) {
            float s = 0.f;
#pragma unroll
            for (int e = 0; e < 8; e++) s += xr[e] * sWq[d*8 + e];
            s *= QSCALE;
            q[qq][d] = pack2(s, s);
        }
    }
    __syncthreads();

    const ull ONE2 = pack2(1.f, 1.f);
    ull acc[4][4];   // [query][dim], lanes = even/odd keys
    ull den[4];
#pragma unroll
    for (int qq = 0; qq < 4; qq++) {
        den[qq] = 0;
#pragma unroll
        for (int d = 0; d < 4; d++) acc[qq][d] = 0;
    }

#pragma unroll 4
    for (int j = 0; j < NPAIR; j++) {
        ulonglong2 kA = sK01[j];     // {k0 pair | k1 pair}
        ulonglong2 kB = sK23[j];     // {k2 pair | k3 pair}
        ulonglong2 vA = sV01[j];
        ulonglong2 vB = sV23[j];
#pragma unroll
        for (int qq = 0; qq < 4; qq++) {
            ull s = mul2p(q[qq][0], kA.x);
            s = fma2p(q[qq][1], kA.y, s);
            s = fma2p(q[qq][2], kB.x, s);
            s = fma2p(q[qq][3], kB.y, s);
            float e0, e1; unpack2(s, e0, e1);
            ull w = pack2(ex2f(e0), ex2f(e1));
            acc[qq][0] = fma2p(w, vA.x, acc[qq][0]);
            acc[qq][1] = fma2p(w, vA.y, acc[qq][1]);
            acc[qq][2] = fma2p(w, vB.x, acc[qq][2]);
            acc[qq][3] = fma2p(w, vB.y, acc[qq][3]);
            den[qq]    = fma2p(w, ONE2, den[qq]);
        }
    }

    // ---- reduce key-pair lanes, atomically accumulate ----
#pragma unroll
    for (int qq = 0; qq < 4; qq++) {
        float lo, hi, s0, s1, s2, s3, dd;
        unpack2(acc[qq][0], lo, hi); s0 = lo + hi;
        unpack2(acc[qq][1], lo, hi); s1 = lo + hi;
        unpack2(acc[qq][2], lo, hi); s2 = lo + hi;
        unpack2(acc[qq][3], lo, hi); s3 = lo + hi;
        unpack2(den[qq],    lo, hi); dd = lo + hi;
        int t = b*NS + qi + qq*128;
        int a = t*2 + h;
        float* pN = (float*)&g_accN[a];
        atomicAdd(pN + 0, s0);
        atomicAdd(pN + 1, s1);
        atomicAdd(pN + 2, s2);
        atomicAdd(pN + 3, s3);
        atomicAdd(&g_accD[a], dd);
    }
}

// ============================================================
// Finalize: read accumulators (coalesced, head pairs in
// adjacent lanes), analytic quantum measurement + Wo, then
// re-zero the accumulators (invariant for next graph replay).
// z_w = prod_{u<=w} cos(o_u + o_{u&3}) (w>=1); z_0 = prod_{u=1..7}.
// ============================================================
__global__ void __launch_bounds__(256) quantum_kernel(const float* __restrict__ Wo,
                                                      float* __restrict__ out) {
    __shared__ float sWo[64];
    int tid = threadIdx.x;
    if (tid < 64) sWo[tid] = Wo[tid];
    __syncthreads();

    int gid = blockIdx.x * 256 + tid;   // = token*2 + head
    int t = gid >> 1;
    int h = gid & 1;

    float4 nn = g_accN[gid];
    float  dd = g_accD[gid];
    float r = rcpf(dd);
    float o0 = nn.x*r, o1 = nn.y*r, o2 = nn.z*r, o3 = nn.w*r;

    // other head's o lives in the adjacent lane
    float p0 = __shfl_xor_sync(0xFFFFFFFFu, o0, 1);
    float p1 = __shfl_xor_sync(0xFFFFFFFFu, o1, 1);
    float p2 = __shfl_xor_sync(0xFFFFFFFFu, o2, 1);
    float p3 = __shfl_xor_sync(0xFFFFFFFFu, o3, 1);

    // c_u for this thread's u = h*4+d: arg = o_u + o_{u&3}
    float a0 = o0 + (h ? p0 : o0);
    float a1 = o1 + (h ? p1 : o1);
    float a2 = o2 + (h ? p2 : o2);
    float a3 = o3 + (h ? p3 : o3);
    float c0 = __cosf(a0), c1 = __cosf(a1), c2 = __cosf(a2), c3 = __cosf(a3);

    // gather all 8 c's
    float q0 = __shfl_xor_sync(0xFFFFFFFFu, c0, 1);
    float q1 = __shfl_xor_sync(0xFFFFFFFFu, c1, 1);
    float q2 = __shfl_xor_sync(0xFFFFFFFFu, c2, 1);
    float q3 = __shfl_xor_sync(0xFFFFFFFFu, c3, 1);
    float gc[8];
    gc[0] = h ? q0 : c0;  gc[1] = h ? q1 : c1;
    gc[2] = h ? q2 : c2;  gc[3] = h ? q3 : c3;
    gc[4] = h ? c0 : q0;  gc[5] = h ? c1 : q1;
    gc[6] = h ? c2 : q2;  gc[7] = h ? c3 : q3;

    // z products
    float z[8];
    float tp = gc[1];
    z[1] = gc[0] * tp;
#pragma unroll
    for (int w = 2; w < 8; w++) { tp *= gc[w]; z[w] = gc[0] * tp; }
    z[0] = tp;

    // this thread's 4 output features f = h*4+i
    float rr[4];
#pragma unroll
    for (int i = 0; i < 4; i++) {
        float sacc = 0.f;
#pragma unroll
        for (int qq = 0; qq < 8; qq++) sacc += z[qq] * sWo[(h*4 + i)*8 + qq];
        rr[i] = sacc;
    }
    ((float4*)out)[gid] = make_float4(rr[0], rr[1], rr[2], rr[3]);

    // restore zero-state for the next replay
    g_accN[gid] = make_float4(0.f, 0.f, 0.f, 0.f);
    g_accD[gid] = 0.f;
}

// ============================================================
extern "C" void kernel_launch(void* const* d_in, const int* in_sizes, int n_in,
                              void* d_out, int out_size) {
    const float* x  = (const float*)d_in[0];
    const float* Wq = (const float*)d_in[1];
    const float* Wk = (const float*)d_in[2];
    const float* Wv = (const float*)d_in[3];
    const float* Wo = (const float*)d_in[4];
    float* out = (float*)d_out;

    attn_kernel<<<dim3(NS/QB, SPLITS, NBH), 128>>>(x, Wq, Wk, Wv);
    quantum_kernel<<<NT*NH/256, 256>>>(Wo, out);
}

// round 8
// speedup vs baseline: 1.0468x; 1.0468x over previous
#include <cuda_runtime.h>

#define NB 8
#define NS 2048
#define NE 8
#define NH 2
#define ND 4
#define NT (NB*NS)        // 16384 tokens
#define NBH (NB*NH)       // 16 (batch, head) pairs
#define SPLITS 8
#define KPS (NS/SPLITS)   // 256 keys per split
#define NPAIR (KPS/2)     // 128 key pairs
#define QB 512            // queries per CTA (4 per thread)

// log2(e) / sqrt(D) folded into q so scores feed ex2 directly
#define QSCALE 0.72134752044448169f

// Accumulators (zero at module load; each launch leaves them zero again)
__device__ float4 g_accN[NT*NH];   // softmax numerators, index = token*2 + head
__device__ float  g_accD[NT*NH];   // softmax denominators

typedef unsigned long long ull;

// ---- packed f32x2 helpers ----
static __device__ __forceinline__ ull pack2(float a, float b) {
    ull r; asm("mov.b64 %0, {%1,%2};" : "=l"(r) : "f"(a), "f"(b)); return r;
}
static __device__ __forceinline__ void unpack2(ull v, float& a, float& b) {
    asm("mov.b64 {%0,%1}, %2;" : "=f"(a), "=f"(b) : "l"(v));
}
static __device__ __forceinline__ ull fma2p(ull a, ull b, ull c) {
    ull d; asm("fma.rn.f32x2 %0, %1, %2, %3;" : "=l"(d) : "l"(a), "l"(b), "l"(c)); return d;
}
static __device__ __forceinline__ ull mul2p(ull a, ull b) {
    ull d; asm("mul.rn.f32x2 %0, %1, %2;" : "=l"(d) : "l"(a), "l"(b)); return d;
}
static __device__ __forceinline__ float ex2f(float x) {
    float r; asm("ex2.approx.f32 %0, %1;" : "=f"(r) : "f"(x)); return r;
}
static __device__ __forceinline__ float rcpf(float x) {
    float r; asm("rcp.approx.f32 %0, %1;" : "=f"(r) : "f"(x)); return r;
}

// ============================================================
// Fused QKV + split-K softmax attention.
// grid = (NS/QB, SPLITS, NBH), 128 threads, 4 queries/thread,
// __launch_bounds__(128,4): 128-reg cap, 16 warps/SM.
// K/V staged key-pair-packed (SoA, conflict-free LDS.128):
// 4 LDS.128 per 2 keys serve 8 scores/thread -> LDS/score 0.5.
// Split results reduced via REDG atomicAdd (no partial bufs).
// ============================================================
__global__ void __launch_bounds__(128, 4) attn_kernel(const float* __restrict__ x,
                                                      const float* __restrict__ Wq,
                                                      const float* __restrict__ Wk,
                                                      const float* __restrict__ Wv) {
    __shared__ float sWq[32], sWk[32], sWv[32];   // this head's 4 rows (4x8)
    __shared__ ulonglong2 sK01[NPAIR];
    __shared__ ulonglong2 sK23[NPAIR];
    __shared__ ulonglong2 sV01[NPAIR];
    __shared__ ulonglong2 sV23[NPAIR];

    const int bh    = blockIdx.z;
    const int split = blockIdx.y;
    const int tid   = threadIdx.x;
    const int b     = bh >> 1;
    const int h     = bh & 1;

    if (tid < 32) {
        sWq[tid] = Wq[h*32 + tid];
        sWk[tid] = Wk[h*32 + tid];
        sWv[tid] = Wv[h*32 + tid];
    }
    __syncthreads();

    const float4* x4 = (const float4*)x;

    // ---- stage one key pair per thread (keys 2*tid, 2*tid+1) ----
    {
        int tokA = b*NS + split*KPS + 2*tid;
        float4 a0 = x4[tokA*2], a1 = x4[tokA*2+1];
        float4 b0 = x4[tokA*2+2], b1 = x4[tokA*2+3];
        float xra[8] = {a0.x,a0.y,a0.z,a0.w,a1.x,a1.y,a1.z,a1.w};
        float xrb[8] = {b0.x,b0.y,b0.z,b0.w,b1.x,b1.y,b1.z,b1.w};
        float kA[4], vA[4], kB[4], vB[4];
#pragma unroll
        for (int d = 0; d < 4; d++) {
            float ka = 0.f, va = 0.f, kb = 0.f, vb = 0.f;
#pragma unroll
            for (int e = 0; e < 8; e++) {
                float wk = sWk[d*8 + e], wv = sWv[d*8 + e];
                ka += xra[e] * wk;  va += xra[e] * wv;
                kb += xrb[e] * wk;  vb += xrb[e] * wv;
            }
            kA[d] = ka; vA[d] = va; kB[d] = kb; vB[d] = vb;
        }
        ulonglong2 t;
        t.x = pack2(kA[0], kB[0]); t.y = pack2(kA[1], kB[1]); sK01[tid] = t;
        t.x = pack2(kA[2], kB[2]); t.y = pack2(kA[3], kB[3]); sK23[tid] = t;
        t.x = pack2(vA[0], vB[0]); t.y = pack2(vA[1], vB[1]); sV01[tid] = t;
        t.x = pack2(vA[2], vB[2]); t.y = pack2(vA[3], vB[3]); sV23[tid] = t;
    }

    // ---- this thread's 4 queries (qi + 128*qq), {q,q}-dup packed ----
    const int qi = blockIdx.x * QB + tid;
    ull q[4][4];
#pragma unroll
    for (int qq = 0; qq < 4; qq++) {
        int ta = b*NS + qi + qq*128;
        float4 a0 = x4[ta*2], a1 = x4[ta*2+1];
        float xr[8] = {a0.x,a0.y,a0.z,a0.w,a1.x,a1.y,a1.z,a1.w};
#pragma unroll
        for (int d = 0; d < 4; d++) {
            float s = 0.f;
#pragma unroll
            for (int e = 0; e < 8; e++) s += xr[e] * sWq[d*8 + e];
            s *= QSCALE;
            q[qq][d] = pack2(s, s);
        }
    }
    __syncthreads();

    const ull ONE2 = pack2(1.f, 1.f);
    ull acc[4][4];   // [query][dim], lanes = even/odd keys
    ull den[4];
#pragma unroll
    for (int qq = 0; qq < 4; qq++) {
        den[qq] = 0;
#pragma unroll
        for (int d = 0; d < 4; d++) acc[qq][d] = 0;
    }

#pragma unroll 2
    for (int j = 0; j < NPAIR; j++) {
        ulonglong2 kA = sK01[j];     // {k0 pair | k1 pair}
        ulonglong2 kB = sK23[j];     // {k2 pair | k3 pair}
        ulonglong2 vA = sV01[j];
        ulonglong2 vB = sV23[j];
#pragma unroll
        for (int qq = 0; qq < 4; qq++) {
            ull s = mul2p(q[qq][0], kA.x);
            s = fma2p(q[qq][1], kA.y, s);
            s = fma2p(q[qq][2], kB.x, s);
            s = fma2p(q[qq][3], kB.y, s);
            float e0, e1; unpack2(s, e0, e1);
            ull w = pack2(ex2f(e0), ex2f(e1));
            acc[qq][0] = fma2p(w, vA.x, acc[qq][0]);
            acc[qq][1] = fma2p(w, vA.y, acc[qq][1]);
            acc[qq][2] = fma2p(w, vB.x, acc[qq][2]);
            acc[qq][3] = fma2p(w, vB.y, acc[qq][3]);
            den[qq]    = fma2p(w, ONE2, den[qq]);
        }
    }

    // ---- reduce key-pair lanes, atomically accumulate ----
#pragma unroll
    for (int qq = 0; qq < 4; qq++) {
        float lo, hi, s0, s1, s2, s3, dd;
        unpack2(acc[qq][0], lo, hi); s0 = lo + hi;
        unpack2(acc[qq][1], lo, hi); s1 = lo + hi;
        unpack2(acc[qq][2], lo, hi); s2 = lo + hi;
        unpack2(acc[qq][3], lo, hi); s3 = lo + hi;
        unpack2(den[qq],    lo, hi); dd = lo + hi;
        int t = b*NS + qi + qq*128;
        int a = t*2 + h;
        float* pN = (float*)&g_accN[a];
        atomicAdd(pN + 0, s0);
        atomicAdd(pN + 1, s1);
        atomicAdd(pN + 2, s2);
        atomicAdd(pN + 3, s3);
        atomicAdd(&g_accD[a], dd);
    }
}

// ============================================================
// Finalize: read accumulators (coalesced, head pairs in
// adjacent lanes), analytic quantum measurement + Wo, then
// re-zero the accumulators (invariant for next graph replay).
// z_w = prod_{u<=w} cos(o_u + o_{u&3}) (w>=1); z_0 = prod_{u=1..7}.
// ============================================================
__global__ void __launch_bounds__(128) quantum_kernel(const float* __restrict__ Wo,
                                                      float* __restrict__ out) {
    __shared__ float sWo[64];
    int tid = threadIdx.x;
    if (tid < 64) sWo[tid] = Wo[tid];

    int gid = blockIdx.x * 128 + tid;   // = token*2 + head
    int t = gid >> 1;
    int h = gid & 1;

    float4 nn = g_accN[gid];
    float  dd = g_accD[gid];
    __syncthreads();
    float r = rcpf(dd);
    float o0 = nn.x*r, o1 = nn.y*r, o2 = nn.z*r, o3 = nn.w*r;

    // other head's o lives in the adjacent lane
    float p0 = __shfl_xor_sync(0xFFFFFFFFu, o0, 1);
    float p1 = __shfl_xor_sync(0xFFFFFFFFu, o1, 1);
    float p2 = __shfl_xor_sync(0xFFFFFFFFu, o2, 1);
    float p3 = __shfl_xor_sync(0xFFFFFFFFu, o3, 1);

    // c_u for this thread's u = h*4+d: arg = o_u + o_{u&3}
    float a0 = o0 + (h ? p0 : o0);
    float a1 = o1 + (h ? p1 : o1);
    float a2 = o2 + (h ? p2 : o2);
    float a3 = o3 + (h ? p3 : o3);
    float c0 = __cosf(a0), c1 = __cosf(a1), c2 = __cosf(a2), c3 = __cosf(a3);

    // gather all 8 c's
    float q0 = __shfl_xor_sync(0xFFFFFFFFu, c0, 1);
    float q1 = __shfl_xor_sync(0xFFFFFFFFu, c1, 1);
    float q2 = __shfl_xor_sync(0xFFFFFFFFu, c2, 1);
    float q3 = __shfl_xor_sync(0xFFFFFFFFu, c3, 1);
    float gc[8];
    gc[0] = h ? q0 : c0;  gc[1] = h ? q1 : c1;
    gc[2] = h ? q2 : c2;  gc[3] = h ? q3 : c3;
    gc[4] = h ? c0 : q0;  gc[5] = h ? c1 : q1;
    gc[6] = h ? c2 : q2;  gc[7] = h ? c3 : q3;

    // z products
    float z[8];
    float tp = gc[1];
    z[1] = gc[0] * tp;
#pragma unroll
    for (int w = 2; w < 8; w++) { tp *= gc[w]; z[w] = gc[0] * tp; }
    z[0] = tp;

    // this thread's 4 output features f = h*4+i
    float rr[4];
#pragma unroll
    for (int i = 0; i < 4; i++) {
        float sacc = 0.f;
#pragma unroll
        for (int qq = 0; qq < 8; qq++) sacc += z[qq] * sWo[(h*4 + i)*8 + qq];
        rr[i] = sacc;
    }
    ((float4*)out)[gid] = make_float4(rr[0], rr[1], rr[2], rr[3]);

    // restore zero-state for the next replay
    g_accN[gid] = make_float4(0.f, 0.f, 0.f, 0.f);
    g_accD[gid] = 0.f;
}

// ============================================================
extern "C" void kernel_launch(void* const* d_in, const int* in_sizes, int n_in,
                              void* d_out, int out_size) {
    const float* x  = (const float*)d_in[0];
    const float* Wq = (const float*)d_in[1];
    const float* Wk = (const float*)d_in[2];
    const float* Wv = (const float*)d_in[3];
    const float* Wo = (const float*)d_in[4];
    float* out = (float*)d_out;

    attn_kernel<<<dim3(NS/QB, SPLITS, NBH), 128>>>(x, Wq, Wk, Wv);
    quantum_kernel<<<NT*NH/128, 128>>>(Wo, out);
}

// round 9
// speedup vs baseline: 1.1050x; 1.0556x over previous
#include <cuda_runtime.h>

#define NB 8
#define NS 2048
#define NE 8
#define NH 2
#define ND 4
#define NT (NB*NS)        // 16384 tokens
#define NBH (NB*NH)       // 16 (batch, head) pairs
#define SPLITS 8
#define KPS (NS/SPLITS)   // 256 keys per split
#define NPAIR (KPS/2)     // 128 key pairs
#define QB 256            // queries per CTA (2 per thread)
#define NQBLK (NS/QB)     // 8 query blocks
#define NCONTRIB (SPLITS*NH)  // 16 CTAs feed one (b, qblock)

// log2(e) / sqrt(D) folded into q so scores feed ex2 directly
#define QSCALE 0.72134752044448169f

// Accumulators + counters (zero at load; every launch restores zeros)
__device__ float4   g_accN[NT*NH];       // numerators, index = token*2 + head
__device__ float    g_accD[NT*NH];       // denominators
__device__ unsigned g_cnt[NB*NQBLK];     // completion counters

typedef unsigned long long ull;

// ---- packed f32x2 helpers ----
static __device__ __forceinline__ ull pack2(float a, float b) {
    ull r; asm("mov.b64 %0, {%1,%2};" : "=l"(r) : "f"(a), "f"(b)); return r;
}
static __device__ __forceinline__ void unpack2(ull v, float& a, float& b) {
    asm("mov.b64 {%0,%1}, %2;" : "=f"(a), "=f"(b) : "l"(v));
}
static __device__ __forceinline__ ull fma2p(ull a, ull b, ull c) {
    ull d; asm("fma.rn.f32x2 %0, %1, %2, %3;" : "=l"(d) : "l"(a), "l"(b), "l"(c)); return d;
}
static __device__ __forceinline__ ull mul2p(ull a, ull b) {
    ull d; asm("mul.rn.f32x2 %0, %1, %2;" : "=l"(d) : "l"(a), "l"(b)); return d;
}
static __device__ __forceinline__ float ex2f(float x) {
    float r; asm("ex2.approx.f32 %0, %1;" : "=f"(r) : "f"(x)); return r;
}
static __device__ __forceinline__ float rcpf(float x) {
    float r; asm("rcp.approx.f32 %0, %1;" : "=f"(r) : "f"(x)); return r;
}

// ============================================================
// Single fused kernel: QKV + split-K softmax attention with
// atomic reduction; the LAST CTA per (b, qblock) finalizes its
// 256 tokens (quantum measurement + Wo) inline.
// grid = (NQBLK, SPLITS, NBH), 128 threads (R6-proven mainloop).
// ============================================================
__global__ void __launch_bounds__(128, 7) fused_kernel(const float* __restrict__ x,
                                                       const float* __restrict__ Wq,
                                                       const float* __restrict__ Wk,
                                                       const float* __restrict__ Wv,
                                                       const float* __restrict__ Wo,
                                                       float* __restrict__ out) {
    __shared__ float sWq[32], sWk[32], sWv[32];   // this head's 4 rows (4x8)
    __shared__ float sWo[64];
    __shared__ ulonglong2 sK01[NPAIR];
    __shared__ ulonglong2 sK23[NPAIR];
    __shared__ ulonglong2 sV01[NPAIR];
    __shared__ ulonglong2 sV23[NPAIR];
    __shared__ unsigned s_old;

    const int bh    = blockIdx.z;
    const int split = blockIdx.y;
    const int tid   = threadIdx.x;
    const int b     = bh >> 1;
    const int h     = bh & 1;

    if (tid < 32) {
        sWq[tid] = Wq[h*32 + tid];
        sWk[tid] = Wk[h*32 + tid];
        sWv[tid] = Wv[h*32 + tid];
    }
    if (tid >= 64) sWo[tid - 64] = Wo[tid - 64];
    __syncthreads();

    const float4* x4 = (const float4*)x;

    // ---- stage one key pair per thread (keys 2*tid, 2*tid+1) ----
    {
        int tokA = b*NS + split*KPS + 2*tid;
        float4 a0 = x4[tokA*2], a1 = x4[tokA*2+1];
        float4 b0 = x4[tokA*2+2], b1 = x4[tokA*2+3];
        float xra[8] = {a0.x,a0.y,a0.z,a0.w,a1.x,a1.y,a1.z,a1.w};
        float xrb[8] = {b0.x,b0.y,b0.z,b0.w,b1.x,b1.y,b1.z,b1.w};
        float kA[4], vA[4], kB[4], vB[4];
#pragma unroll
        for (int d = 0; d < 4; d++) {
            float ka = 0.f, va = 0.f, kb = 0.f, vb = 0.f;
#pragma unroll
            for (int e = 0; e < 8; e++) {
                float wk = sWk[d*8 + e], wv = sWv[d*8 + e];
                ka += xra[e] * wk;  va += xra[e] * wv;
                kb += xrb[e] * wk;  vb += xrb[e] * wv;
            }
            kA[d] = ka; vA[d] = va; kB[d] = kb; vB[d] = vb;
        }
        ulonglong2 t;
        t.x = pack2(kA[0], kB[0]); t.y = pack2(kA[1], kB[1]); sK01[tid] = t;
        t.x = pack2(kA[2], kB[2]); t.y = pack2(kA[3], kB[3]); sK23[tid] = t;
        t.x = pack2(vA[0], vB[0]); t.y = pack2(vA[1], vB[1]); sV01[tid] = t;
        t.x = pack2(vA[2], vB[2]); t.y = pack2(vA[3], vB[3]); sV23[tid] = t;
    }

    // ---- this thread's 2 queries (qa = qi, qb = qi+128), {q,q}-packed ----
    const int qi = blockIdx.x * QB + tid;
    ull qa[4], qb[4];
    {
        int ta = b*NS + qi, tb = ta + 128;
        float4 a0 = x4[ta*2], a1 = x4[ta*2+1];
        float4 b0 = x4[tb*2], b1 = x4[tb*2+1];
        float xra[8] = {a0.x,a0.y,a0.z,a0.w,a1.x,a1.y,a1.z,a1.w};
        float xrb[8] = {b0.x,b0.y,b0.z,b0.w,b1.x,b1.y,b1.z,b1.w};
#pragma unroll
        for (int d = 0; d < 4; d++) {
            float sa = 0.f, sb = 0.f;
#pragma unroll
            for (int e = 0; e < 8; e++) {
                float w = sWq[d*8 + e];
                sa += xra[e] * w;
                sb += xrb[e] * w;
            }
            qa[d] = pack2(sa * QSCALE, sa * QSCALE);
            qb[d] = pack2(sb * QSCALE, sb * QSCALE);
        }
    }
    __syncthreads();

    const ull ONE2 = pack2(1.f, 1.f);
    ull na0 = 0, na1 = 0, na2 = 0, na3 = 0;
    ull nb0 = 0, nb1 = 0, nb2 = 0, nb3 = 0;
    ull dap = 0, dbp = 0;

#pragma unroll 8
    for (int j = 0; j < NPAIR; j++) {
        ulonglong2 kA = sK01[j];     // {k0 pair | k1 pair}
        ulonglong2 kB = sK23[j];     // {k2 pair | k3 pair}
        ull sa = mul2p(qa[0], kA.x);
        ull sb = mul2p(qb[0], kA.x);
        sa = fma2p(qa[1], kA.y, sa);
        sb = fma2p(qb[1], kA.y, sb);
        sa = fma2p(qa[2], kB.x, sa);
        sb = fma2p(qb[2], kB.x, sb);
        sa = fma2p(qa[3], kB.y, sa);
        sb = fma2p(qb[3], kB.y, sb);
        float s0, s1, s2, s3;
        unpack2(sa, s0, s1);
        unpack2(sb, s2, s3);
        ull wa = pack2(ex2f(s0), ex2f(s1));
        ull wb = pack2(ex2f(s2), ex2f(s3));
        ulonglong2 vA = sV01[j];
        ulonglong2 vB = sV23[j];
        na0 = fma2p(wa, vA.x, na0);
        na1 = fma2p(wa, vA.y, na1);
        na2 = fma2p(wa, vB.x, na2);
        na3 = fma2p(wa, vB.y, na3);
        nb0 = fma2p(wb, vA.x, nb0);
        nb1 = fma2p(wb, vA.y, nb1);
        nb2 = fma2p(wb, vB.x, nb2);
        nb3 = fma2p(wb, vB.y, nb3);
        dap = fma2p(wa, ONE2, dap);
        dbp = fma2p(wb, ONE2, dbp);
    }

    // ---- reduce key-pair lanes, atomically accumulate ----
    {
        float lo, hi, s0, s1, s2, s3, dd;
        int a0 = (b*NS + qi)*2 + h;
        unpack2(na0, lo, hi); s0 = lo + hi;
        unpack2(na1, lo, hi); s1 = lo + hi;
        unpack2(na2, lo, hi); s2 = lo + hi;
        unpack2(na3, lo, hi); s3 = lo + hi;
        unpack2(dap, lo, hi); dd = lo + hi;
        float* pN = (float*)&g_accN[a0];
        atomicAdd(pN + 0, s0);
        atomicAdd(pN + 1, s1);
        atomicAdd(pN + 2, s2);
        atomicAdd(pN + 3, s3);
        atomicAdd(&g_accD[a0], dd);

        int a1 = a0 + 256;   // (qi+128)*2 + h
        unpack2(nb0, lo, hi); s0 = lo + hi;
        unpack2(nb1, lo, hi); s1 = lo + hi;
        unpack2(nb2, lo, hi); s2 = lo + hi;
        unpack2(nb3, lo, hi); s3 = lo + hi;
        unpack2(dbp, lo, hi); dd = lo + hi;
        pN = (float*)&g_accN[a1];
        atomicAdd(pN + 0, s0);
        atomicAdd(pN + 1, s1);
        atomicAdd(pN + 2, s2);
        atomicAdd(pN + 3, s3);
        atomicAdd(&g_accD[a1], dd);
    }

    // ---- completion counter: last of 16 contributors finalizes ----
    __threadfence();
    const int cidx = b*NQBLK + blockIdx.x;
    if (tid == 0) s_old = atomicAdd(&g_cnt[cidx], 1u);
    __syncthreads();
    if (s_old != NCONTRIB - 1) return;

    // ============ finalize 256 tokens (2 per thread) ============
    __threadfence();
#pragma unroll
    for (int half = 0; half < 2; half++) {
        int t = b*NS + blockIdx.x*QB + half*128 + tid;
        int a = t*2;
        float4 nA = __ldcg(&g_accN[a]);
        float4 nB = __ldcg(&g_accN[a+1]);
        float  dA = __ldcg(&g_accD[a]);
        float  dB = __ldcg(&g_accD[a+1]);
        float rA = rcpf(dA), rB = rcpf(dB);
        float o0 = nA.x*rA, o1 = nA.y*rA, o2 = nA.z*rA, o3 = nA.w*rA;
        float o4 = nB.x*rB, o5 = nB.y*rB, o6 = nB.z*rB, o7 = nB.w*rB;

        // c_u = cos(o_u + o_{u&3})
        float gc[8];
        gc[0] = __cosf(o0 + o0);
        gc[1] = __cosf(o1 + o1);
        gc[2] = __cosf(o2 + o2);
        gc[3] = __cosf(o3 + o3);
        gc[4] = __cosf(o4 + o0);
        gc[5] = __cosf(o5 + o1);
        gc[6] = __cosf(o6 + o2);
        gc[7] = __cosf(o7 + o3);

        // z_w = prod_{u<=w} gc_u (w>=1); z_0 = prod_{u=1..7}
        float z[8];
        float tp = gc[1];
        z[1] = gc[0] * tp;
#pragma unroll
        for (int w = 2; w < 8; w++) { tp *= gc[w]; z[w] = gc[0] * tp; }
        z[0] = tp;

        // out[t] = z @ Wo^T
        float rr[8];
#pragma unroll
        for (int f = 0; f < 8; f++) {
            float sacc = 0.f;
#pragma unroll
            for (int qq = 0; qq < 8; qq++) sacc += z[qq] * sWo[f*8 + qq];
            rr[f] = sacc;
        }
        float4* o4p = (float4*)out;
        o4p[t*2]   = make_float4(rr[0], rr[1], rr[2], rr[3]);
        o4p[t*2+1] = make_float4(rr[4], rr[5], rr[6], rr[7]);

        // restore zero-state for the next graph replay
        g_accN[a]   = make_float4(0.f, 0.f, 0.f, 0.f);
        g_accN[a+1] = make_float4(0.f, 0.f, 0.f, 0.f);
        g_accD[a]   = 0.f;
        g_accD[a+1] = 0.f;
    }
    if (tid == 0) g_cnt[cidx] = 0u;
}

// ============================================================
extern "C" void kernel_launch(void* const* d_in, const int* in_sizes, int n_in,
                              void* d_out, int out_size) {
    const float* x  = (const float*)d_in[0];
    const float* Wq = (const float*)d_in[1];
    const float* Wk = (const float*)d_in[2];
    const float* Wv = (const float*)d_in[3];
    const float* Wo = (const float*)d_in[4];
    float* out = (float*)d_out;

    fused_kernel<<<dim3(NQBLK, SPLITS, NBH), 128>>>(x, Wq, Wk, Wv, Wo, out);
}

// round 10
// speedup vs baseline: 1.1550x; 1.0452x over previous
#include <cuda_runtime.h>

#define NB 8
#define NS 2048
#define NE 8
#define NH 2
#define ND 4
#define NT (NB*NS)        // 16384 tokens
#define NBH (NB*NH)       // 16 (batch, head) pairs
#define SPLITS 16
#define KPS (NS/SPLITS)   // 128 keys per split
#define NPAIR (KPS/2)     // 64 key pairs
#define QB 256            // queries per CTA (2 per thread)

// log2(e) / sqrt(D) folded into q so scores feed ex2 directly
#define QSCALE 0.72134752044448169f

// Accumulators (zero at module load; quantum kernel re-zeroes after reading)
__device__ float4 g_accN[NT*NH];   // numerators, index = token*2 + head
__device__ float  g_accD[NT*NH];   // denominators

typedef unsigned long long ull;

// ---- packed f32x2 helpers ----
static __device__ __forceinline__ ull pack2(float a, float b) {
    ull r; asm("mov.b64 %0, {%1,%2};" : "=l"(r) : "f"(a), "f"(b)); return r;
}
static __device__ __forceinline__ void unpack2(ull v, float& a, float& b) {
    asm("mov.b64 {%0,%1}, %2;" : "=f"(a), "=f"(b) : "l"(v));
}
static __device__ __forceinline__ ull fma2p(ull a, ull b, ull c) {
    ull d; asm("fma.rn.f32x2 %0, %1, %2, %3;" : "=l"(d) : "l"(a), "l"(b), "l"(c)); return d;
}
static __device__ __forceinline__ ull mul2p(ull a, ull b) {
    ull d; asm("mul.rn.f32x2 %0, %1, %2;" : "=l"(d) : "l"(a), "l"(b)); return d;
}
static __device__ __forceinline__ float ex2f(float x) {
    float r; asm("ex2.approx.f32 %0, %1;" : "=f"(r) : "f"(x)); return r;
}
static __device__ __forceinline__ float rcpf(float x) {
    float r; asm("rcp.approx.f32 %0, %1;" : "=f"(r) : "f"(x)); return r;
}

// ============================================================
// Fused QKV + split-K softmax attention, atomic reduction.
// grid = (NS/QB, SPLITS, NBH) = (8,16,16) = 2048 CTAs,
// __launch_bounds__(128,8): <=64 regs, 8 CTAs/SM, 32 warps/SM.
// K/V staged key-pair-packed (SoA, conflict-free LDS.128).
// ============================================================
__global__ void __launch_bounds__(128, 8) attn_kernel(const float* __restrict__ x,
                                                      const float* __restrict__ Wq,
                                                      const float* __restrict__ Wk,
                                                      const float* __restrict__ Wv) {
    __shared__ float sWq[32], sWk[32], sWv[32];   // this head's 4 rows (4x8)
    __shared__ ulonglong2 sK01[NPAIR];
    __shared__ ulonglong2 sK23[NPAIR];
    __shared__ ulonglong2 sV01[NPAIR];
    __shared__ ulonglong2 sV23[NPAIR];

    const int bh    = blockIdx.z;
    const int split = blockIdx.y;
    const int tid   = threadIdx.x;
    const int b     = bh >> 1;
    const int h     = bh & 1;

    if (tid < 32) {
        sWq[tid] = Wq[h*32 + tid];
        sWk[tid] = Wk[h*32 + tid];
        sWv[tid] = Wv[h*32 + tid];
    }
    __syncthreads();

    const float4* x4 = (const float4*)x;

    // ---- stage one key pair per thread (threads 0..NPAIR-1) ----
    if (tid < NPAIR) {
        int tokA = b*NS + split*KPS + 2*tid;
        float4 a0 = x4[tokA*2], a1 = x4[tokA*2+1];
        float4 b0 = x4[tokA*2+2], b1 = x4[tokA*2+3];
        float xra[8] = {a0.x,a0.y,a0.z,a0.w,a1.x,a1.y,a1.z,a1.w};
        float xrb[8] = {b0.x,b0.y,b0.z,b0.w,b1.x,b1.y,b1.z,b1.w};
        float kA[4], vA[4], kB[4], vB[4];
#pragma unroll
        for (int d = 0; d < 4; d++) {
            float ka = 0.f, va = 0.f, kb = 0.f, vb = 0.f;
#pragma unroll
            for (int e = 0; e < 8; e++) {
                float wk = sWk[d*8 + e], wv = sWv[d*8 + e];
                ka += xra[e] * wk;  va += xra[e] * wv;
                kb += xrb[e] * wk;  vb += xrb[e] * wv;
            }
            kA[d] = ka; vA[d] = va; kB[d] = kb; vB[d] = vb;
        }
        ulonglong2 t;
        t.x = pack2(kA[0], kB[0]); t.y = pack2(kA[1], kB[1]); sK01[tid] = t;
        t.x = pack2(kA[2], kB[2]); t.y = pack2(kA[3], kB[3]); sK23[tid] = t;
        t.x = pack2(vA[0], vB[0]); t.y = pack2(vA[1], vB[1]); sV01[tid] = t;
        t.x = pack2(vA[2], vB[2]); t.y = pack2(vA[3], vB[3]); sV23[tid] = t;
    }

    // ---- this thread's 2 queries (qa = qi, qb = qi+128), {q,q}-packed ----
    const int qi = blockIdx.x * QB + tid;
    ull qa[4], qb[4];
    {
        int ta = b*NS + qi, tb = ta + 128;
        float4 a0 = x4[ta*2], a1 = x4[ta*2+1];
        float4 b0 = x4[tb*2], b1 = x4[tb*2+1];
        float xra[8] = {a0.x,a0.y,a0.z,a0.w,a1.x,a1.y,a1.z,a1.w};
        float xrb[8] = {b0.x,b0.y,b0.z,b0.w,b1.x,b1.y,b1.z,b1.w};
#pragma unroll
        for (int d = 0; d < 4; d++) {
            float sa = 0.f, sb = 0.f;
#pragma unroll
            for (int e = 0; e < 8; e++) {
                float w = sWq[d*8 + e];
                sa += xra[e] * w;
                sb += xrb[e] * w;
            }
            qa[d] = pack2(sa * QSCALE, sa * QSCALE);
            qb[d] = pack2(sb * QSCALE, sb * QSCALE);
        }
    }
    __syncthreads();

    const ull ONE2 = pack2(1.f, 1.f);
    ull na0 = 0, na1 = 0, na2 = 0, na3 = 0;
    ull nb0 = 0, nb1 = 0, nb2 = 0, nb3 = 0;
    ull dap = 0, dbp = 0;

#pragma unroll 4
    for (int j = 0; j < NPAIR; j++) {
        ulonglong2 kA = sK01[j];     // {k0 pair | k1 pair}
        ulonglong2 kB = sK23[j];     // {k2 pair | k3 pair}
        ull sa = mul2p(qa[0], kA.x);
        ull sb = mul2p(qb[0], kA.x);
        sa = fma2p(qa[1], kA.y, sa);
        sb = fma2p(qb[1], kA.y, sb);
        sa = fma2p(qa[2], kB.x, sa);
        sb = fma2p(qb[2], kB.x, sb);
        sa = fma2p(qa[3], kB.y, sa);
        sb = fma2p(qb[3], kB.y, sb);
        float s0, s1, s2, s3;
        unpack2(sa, s0, s1);
        unpack2(sb, s2, s3);
        ull wa = pack2(ex2f(s0), ex2f(s1));
        ull wb = pack2(ex2f(s2), ex2f(s3));
        ulonglong2 vA = sV01[j];
        ulonglong2 vB = sV23[j];
        na0 = fma2p(wa, vA.x, na0);
        na1 = fma2p(wa, vA.y, na1);
        na2 = fma2p(wa, vB.x, na2);
        na3 = fma2p(wa, vB.y, na3);
        nb0 = fma2p(wb, vA.x, nb0);
        nb1 = fma2p(wb, vA.y, nb1);
        nb2 = fma2p(wb, vB.x, nb2);
        nb3 = fma2p(wb, vB.y, nb3);
        dap = fma2p(wa, ONE2, dap);
        dbp = fma2p(wb, ONE2, dbp);
    }

    // ---- reduce key-pair lanes, atomically accumulate ----
    {
        float lo, hi, s0, s1, s2, s3, dd;
        int a0 = (b*NS + qi)*2 + h;
        unpack2(na0, lo, hi); s0 = lo + hi;
        unpack2(na1, lo, hi); s1 = lo + hi;
        unpack2(na2, lo, hi); s2 = lo + hi;
        unpack2(na3, lo, hi); s3 = lo + hi;
        unpack2(dap, lo, hi); dd = lo + hi;
        float* pN = (float*)&g_accN[a0];
        atomicAdd(pN + 0, s0);
        atomicAdd(pN + 1, s1);
        atomicAdd(pN + 2, s2);
        atomicAdd(pN + 3, s3);
        atomicAdd(&g_accD[a0], dd);

        int a1 = a0 + 256;   // (qi+128)*2 + h
        unpack2(nb0, lo, hi); s0 = lo + hi;
        unpack2(nb1, lo, hi); s1 = lo + hi;
        unpack2(nb2, lo, hi); s2 = lo + hi;
        unpack2(nb3, lo, hi); s3 = lo + hi;
        unpack2(dbp, lo, hi); dd = lo + hi;
        pN = (float*)&g_accN[a1];
        atomicAdd(pN + 0, s0);
        atomicAdd(pN + 1, s1);
        atomicAdd(pN + 2, s2);
        atomicAdd(pN + 3, s3);
        atomicAdd(&g_accD[a1], dd);
    }
}

// ============================================================
// Finalize: read accumulators (coalesced, head pairs adjacent
// lanes), analytic quantum measurement + Wo, re-zero accs.
// z_w = prod_{u<=w} cos(o_u + o_{u&3}) (w>=1); z_0 = prod_{u=1..7}.
// ============================================================
__global__ void __launch_bounds__(256) quantum_kernel(const float* __restrict__ Wo,
                                                      float* __restrict__ out) {
    __shared__ float sWo[64];
    int tid = threadIdx.x;
    if (tid < 64) sWo[tid] = Wo[tid];
    __syncthreads();

    int gid = blockIdx.x * 256 + tid;   // = token*2 + head
    int t = gid >> 1;
    int h = gid & 1;

    float4 nn = g_accN[gid];
    float  dd = g_accD[gid];
    float r = rcpf(dd);
    float o0 = nn.x*r, o1 = nn.y*r, o2 = nn.z*r, o3 = nn.w*r;

    // other head's o lives in the adjacent lane
    float p0 = __shfl_xor_sync(0xFFFFFFFFu, o0, 1);
    float p1 = __shfl_xor_sync(0xFFFFFFFFu, o1, 1);
    float p2 = __shfl_xor_sync(0xFFFFFFFFu, o2, 1);
    float p3 = __shfl_xor_sync(0xFFFFFFFFu, o3, 1);

    // c_u for this thread's u = h*4+d: arg = o_u + o_{u&3}
    float a0 = o0 + (h ? p0 : o0);
    float a1 = o1 + (h ? p1 : o1);
    float a2 = o2 + (h ? p2 : o2);
    float a3 = o3 + (h ? p3 : o3);
    float c0 = __cosf(a0), c1 = __cosf(a1), c2 = __cosf(a2), c3 = __cosf(a3);

    // gather all 8 c's
    float q0 = __shfl_xor_sync(0xFFFFFFFFu, c0, 1);
    float q1 = __shfl_xor_sync(0xFFFFFFFFu, c1, 1);
    float q2 = __shfl_xor_sync(0xFFFFFFFFu, c2, 1);
    float q3 = __shfl_xor_sync(0xFFFFFFFFu, c3, 1);
    float gc[8];
    gc[0] = h ? q0 : c0;  gc[1] = h ? q1 : c1;
    gc[2] = h ? q2 : c2;  gc[3] = h ? q3 : c3;
    gc[4] = h ? c0 : q0;  gc[5] = h ? c1 : q1;
    gc[6] = h ? c2 : q2;  gc[7] = h ? c3 : q3;

    // z products
    float z[8];
    float tp = gc[1];
    z[1] = gc[0] * tp;
#pragma unroll
    for (int w = 2; w < 8; w++) { tp *= gc[w]; z[w] = gc[0] * tp; }
    z[0] = tp;

    // this thread's 4 output features f = h*4+i
    float rr[4];
#pragma unroll
    for (int i = 0; i < 4; i++) {
        float sacc = 0.f;
#pragma unroll
        for (int qq = 0; qq < 8; qq++) sacc += z[qq] * sWo[(h*4 + i)*8 + qq];
        rr[i] = sacc;
    }
    ((float4*)out)[gid] = make_float4(rr[0], rr[1], rr[2], rr[3]);

    // restore zero-state for the next replay
    g_accN[gid] = make_float4(0.f, 0.f, 0.f, 0.f);
    g_accD[gid] = 0.f;
}

// ============================================================
extern "C" void kernel_launch(void* const* d_in, const int* in_sizes, int n_in,
                              void* d_out, int out_size) {
    const float* x  = (const float*)d_in[0];
    const float* Wq = (const float*)d_in[1];
    const float* Wk = (const float*)d_in[2];
    const float* Wv = (const float*)d_in[3];
    const float* Wo = (const float*)d_in[4];
    float* out = (float*)d_out;

    attn_kernel<<<dim3(NS/QB, SPLITS, NBH), 128>>>(x, Wq, Wk, Wv);
    quantum_kernel<<<NT*NH/256, 256>>>(Wo, out);
}

// round 11
// speedup vs baseline: 1.1615x; 1.0057x over previous
#include <cuda_runtime.h>

#define NB 8
#define NS 2048
#define NE 8
#define NH 2
#define ND 4
#define NT (NB*NS)        // 16384 tokens
#define NBH (NB*NH)       // 16 (batch, head) pairs
#define SPLITS 8
#define KPS (NS/SPLITS)   // 256 keys per split
#define NPAIR (KPS/2)     // 128 key pairs
#define QB 256            // queries per CTA (2 per thread)

// log2(e) / sqrt(D) folded into q so scores feed ex2 directly
#define QSCALE 0.72134752044448169f

// Accumulators (zero at module load; quantum kernel re-zeroes after reading)
__device__ float4 g_accN[NT*NH];   // numerators, index = token*2 + head
__device__ float  g_accD[NT*NH];   // denominators

typedef unsigned long long ull;

// ---- packed f32x2 helpers ----
static __device__ __forceinline__ ull pack2(float a, float b) {
    ull r; asm("mov.b64 %0, {%1,%2};" : "=l"(r) : "f"(a), "f"(b)); return r;
}
static __device__ __forceinline__ void unpack2(ull v, float& a, float& b) {
    asm("mov.b64 {%0,%1}, %2;" : "=f"(a), "=f"(b) : "l"(v));
}
static __device__ __forceinline__ ull fma2p(ull a, ull b, ull c) {
    ull d; asm("fma.rn.f32x2 %0, %1, %2, %3;" : "=l"(d) : "l"(a), "l"(b), "l"(c)); return d;
}
static __device__ __forceinline__ ull mul2p(ull a, ull b) {
    ull d; asm("mul.rn.f32x2 %0, %1, %2;" : "=l"(d) : "l"(a), "l"(b)); return d;
}
static __device__ __forceinline__ float ex2f(float x) {
    float r; asm("ex2.approx.f32 %0, %1;" : "=f"(r) : "f"(x)); return r;
}
static __device__ __forceinline__ float rcpf(float x) {
    float r; asm("rcp.approx.f32 %0, %1;" : "=f"(r) : "f"(x)); return r;
}

// ============================================================
// Fused QKV + split-K softmax attention (R6-proven mainloop:
// SPLITS=8, QB=256, bounds(128,7), unroll 8), atomic output.
// K/V staged key-pair-packed (SoA, conflict-free LDS.128).
// ============================================================
__global__ void __launch_bounds__(128, 7) attn_kernel(const float* __restrict__ x,
                                                      const float* __restrict__ Wq,
                                                      const float* __restrict__ Wk,
                                                      const float* __restrict__ Wv) {
    __shared__ float sWq[32], sWk[32], sWv[32];   // this head's 4 rows (4x8)
    __shared__ ulonglong2 sK01[NPAIR];
    __shared__ ulonglong2 sK23[NPAIR];
    __shared__ ulonglong2 sV01[NPAIR];
    __shared__ ulonglong2 sV23[NPAIR];

    const int bh    = blockIdx.z;
    const int split = blockIdx.y;
    const int tid   = threadIdx.x;
    const int b     = bh >> 1;
    const int h     = bh & 1;

    if (tid < 32) {
        sWq[tid] = Wq[h*32 + tid];
        sWk[tid] = Wk[h*32 + tid];
        sWv[tid] = Wv[h*32 + tid];
    }
    __syncthreads();

    const float4* x4 = (const float4*)x;

    // ---- stage one key pair per thread (keys 2*tid, 2*tid+1) ----
    {
        int tokA = b*NS + split*KPS + 2*tid;
        float4 a0 = x4[tokA*2], a1 = x4[tokA*2+1];
        float4 b0 = x4[tokA*2+2], b1 = x4[tokA*2+3];
        float xra[8] = {a0.x,a0.y,a0.z,a0.w,a1.x,a1.y,a1.z,a1.w};
        float xrb[8] = {b0.x,b0.y,b0.z,b0.w,b1.x,b1.y,b1.z,b1.w};
        float kA[4], vA[4], kB[4], vB[4];
#pragma unroll
        for (int d = 0; d < 4; d++) {
            float ka = 0.f, va = 0.f, kb = 0.f, vb = 0.f;
#pragma unroll
            for (int e = 0; e < 8; e++) {
                float wk = sWk[d*8 + e], wv = sWv[d*8 + e];
                ka += xra[e] * wk;  va += xra[e] * wv;
                kb += xrb[e] * wk;  vb += xrb[e] * wv;
            }
            kA[d] = ka; vA[d] = va; kB[d] = kb; vB[d] = vb;
        }
        ulonglong2 t;
        t.x = pack2(kA[0], kB[0]); t.y = pack2(kA[1], kB[1]); sK01[tid] = t;
        t.x = pack2(kA[2], kB[2]); t.y = pack2(kA[3], kB[3]); sK23[tid] = t;
        t.x = pack2(vA[0], vB[0]); t.y = pack2(vA[1], vB[1]); sV01[tid] = t;
        t.x = pack2(vA[2], vB[2]); t.y = pack2(vA[3], vB[3]); sV23[tid] = t;
    }

    // ---- this thread's 2 queries (qa = qi, qb = qi+128), {q,q}-packed ----
    const int qi = blockIdx.x * QB + tid;
    ull qa[4], qb[4];
    {
        int ta = b*NS + qi, tb = ta + 128;
        float4 a0 = x4[ta*2], a1 = x4[ta*2+1];
        float4 b0 = x4[tb*2], b1 = x4[tb*2+1];
        float xra[8] = {a0.x,a0.y,a0.z,a0.w,a1.x,a1.y,a1.z,a1.w};
        float xrb[8] = {b0.x,b0.y,b0.z,b0.w,b1.x,b1.y,b1.z,b1.w};
#pragma unroll
        for (int d = 0; d < 4; d++) {
            float sa = 0.f, sb = 0.f;
#pragma unroll
            for (int e = 0; e < 8; e++) {
                float w = sWq[d*8 + e];
                sa += xra[e] * w;
                sb += xrb[e] * w;
            }
            qa[d] = pack2(sa * QSCALE, sa * QSCALE);
            qb[d] = pack2(sb * QSCALE, sb * QSCALE);
        }
    }
    __syncthreads();

    const ull ONE2 = pack2(1.f, 1.f);
    ull na0 = 0, na1 = 0, na2 = 0, na3 = 0;
    ull nb0 = 0, nb1 = 0, nb2 = 0, nb3 = 0;
    ull dap = 0, dbp = 0;

#pragma unroll 8
    for (int j = 0; j < NPAIR; j++) {
        ulonglong2 kA = sK01[j];     // {k0 pair | k1 pair}
        ulonglong2 kB = sK23[j];     // {k2 pair | k3 pair}
        ull sa = mul2p(qa[0], kA.x);
        ull sb = mul2p(qb[0], kA.x);
        sa = fma2p(qa[1], kA.y, sa);
        sb = fma2p(qb[1], kA.y, sb);
        sa = fma2p(qa[2], kB.x, sa);
        sb = fma2p(qb[2], kB.x, sb);
        sa = fma2p(qa[3], kB.y, sa);
        sb = fma2p(qb[3], kB.y, sb);
        float s0, s1, s2, s3;
        unpack2(sa, s0, s1);
        unpack2(sb, s2, s3);
        ull wa = pack2(ex2f(s0), ex2f(s1));
        ull wb = pack2(ex2f(s2), ex2f(s3));
        ulonglong2 vA = sV01[j];
        ulonglong2 vB = sV23[j];
        na0 = fma2p(wa, vA.x, na0);
        na1 = fma2p(wa, vA.y, na1);
        na2 = fma2p(wa, vB.x, na2);
        na3 = fma2p(wa, vB.y, na3);
        nb0 = fma2p(wb, vA.x, nb0);
        nb1 = fma2p(wb, vA.y, nb1);
        nb2 = fma2p(wb, vB.x, nb2);
        nb3 = fma2p(wb, vB.y, nb3);
        dap = fma2p(wa, ONE2, dap);
        dbp = fma2p(wb, ONE2, dbp);
    }

    // ---- reduce key-pair lanes, atomically accumulate ----
    {
        float lo, hi, s0, s1, s2, s3, dd;
        int a0 = (b*NS + qi)*2 + h;
        unpack2(na0, lo, hi); s0 = lo + hi;
        unpack2(na1, lo, hi); s1 = lo + hi;
        unpack2(na2, lo, hi); s2 = lo + hi;
        unpack2(na3, lo, hi); s3 = lo + hi;
        unpack2(dap, lo, hi); dd = lo + hi;
        float* pN = (float*)&g_accN[a0];
        atomicAdd(pN + 0, s0);
        atomicAdd(pN + 1, s1);
        atomicAdd(pN + 2, s2);
        atomicAdd(pN + 3, s3);
        atomicAdd(&g_accD[a0], dd);

        int a1 = a0 + 256;   // (qi+128)*2 + h
        unpack2(nb0, lo, hi); s0 = lo + hi;
        unpack2(nb1, lo, hi); s1 = lo + hi;
        unpack2(nb2, lo, hi); s2 = lo + hi;
        unpack2(nb3, lo, hi); s3 = lo + hi;
        unpack2(dbp, lo, hi); dd = lo + hi;
        pN = (float*)&g_accN[a1];
        atomicAdd(pN + 0, s0);
        atomicAdd(pN + 1, s1);
        atomicAdd(pN + 2, s2);
        atomicAdd(pN + 3, s3);
        atomicAdd(&g_accD[a1], dd);
    }
}

// ============================================================
// Finalize: accumulator LDGs issued FIRST (overlap latency with
// sWo staging + sync), analytic quantum measurement + Wo,
// re-zero accumulators for next graph replay.
// z_w = prod_{u<=w} cos(o_u + o_{u&3}) (w>=1); z_0 = prod_{u=1..7}.
// ============================================================
__global__ void __launch_bounds__(256) quantum_kernel(const float* __restrict__ Wo,
                                                      float* __restrict__ out) {
    __shared__ float sWo[64];
    int tid = threadIdx.x;
    int gid = blockIdx.x * 256 + tid;   // = token*2 + head

    // fire the long-latency loads immediately
    float4 nn = g_accN[gid];
    float  dd = g_accD[gid];

    if (tid < 64) sWo[tid] = Wo[tid];
    __syncthreads();

    int h = gid & 1;
    float r = rcpf(dd);
    float o0 = nn.x*r, o1 = nn.y*r, o2 = nn.z*r, o3 = nn.w*r;

    // other head's o lives in the adjacent lane
    float p0 = __shfl_xor_sync(0xFFFFFFFFu, o0, 1);
    float p1 = __shfl_xor_sync(0xFFFFFFFFu, o1, 1);
    float p2 = __shfl_xor_sync(0xFFFFFFFFu, o2, 1);
    float p3 = __shfl_xor_sync(0xFFFFFFFFu, o3, 1);

    // c_u for this thread's u = h*4+d: arg = o_u + o_{u&3}
    float a0 = o0 + (h ? p0 : o0);
    float a1 = o1 + (h ? p1 : o1);
    float a2 = o2 + (h ? p2 : o2);
    float a3 = o3 + (h ? p3 : o3);
    float c0 = __cosf(a0), c1 = __cosf(a1), c2 = __cosf(a2), c3 = __cosf(a3);

    // gather all 8 c's
    float q0 = __shfl_xor_sync(0xFFFFFFFFu, c0, 1);
    float q1 = __shfl_xor_sync(0xFFFFFFFFu, c1, 1);
    float q2 = __shfl_xor_sync(0xFFFFFFFFu, c2, 1);
    float q3 = __shfl_xor_sync(0xFFFFFFFFu, c3, 1);
    float gc[8];
    gc[0] = h ? q0 : c0;  gc[1] = h ? q1 : c1;
    gc[2] = h ? q2 : c2;  gc[3] = h ? q3 : c3;
    gc[4] = h ? c0 : q0;  gc[5] = h ? c1 : q1;
    gc[6] = h ? c2 : q2;  gc[7] = h ? c3 : q3;

    // z products
    float z[8];
    float tp = gc[1];
    z[1] = gc[0] * tp;
#pragma unroll
    for (int w = 2; w < 8; w++) { tp *= gc[w]; z[w] = gc[0] * tp; }
    z[0] = tp;

    // this thread's 4 output features f = h*4+i
    float rr[4];
#pragma unroll
    for (int i = 0; i < 4; i++) {
        float sacc = 0.f;
#pragma unroll
        for (int qq = 0; qq < 8; qq++) sacc += z[qq] * sWo[(h*4 + i)*8 + qq];
        rr[i] = sacc;
    }
    ((float4*)out)[gid] = make_float4(rr[0], rr[1], rr[2], rr[3]);

    // restore zero-state for the next replay
    g_accN[gid] = make_float4(0.f, 0.f, 0.f, 0.f);
    g_accD[gid] = 0.f;
}

// ============================================================
extern "C" void kernel_launch(void* const* d_in, const int* in_sizes, int n_in,
                              void* d_out, int out_size) {
    const float* x  = (const float*)d_in[0];
    const float* Wq = (const float*)d_in[1];
    const float* Wk = (const float*)d_in[2];
    const float* Wv = (const float*)d_in[3];
    const float* Wo = (const float*)d_in[4];
    float* out = (float*)d_out;

    attn_kernel<<<dim3(NS/QB, SPLITS, NBH), 128>>>(x, Wq, Wk, Wv);
    quantum_kernel<<<NT*NH/256, 256>>>(Wo, out);
}